// round 5
// baseline (speedup 1.0000x reference)
#include <cuda_runtime.h>
#include <cuda_bf16.h>
#include <cuda_fp16.h>
#include <math.h>
#include <stdint.h>

#define NN 100000
#define EE 1600000
#define DH 128
#define DOUT 64
#define NCHUNK 98   // ceil(NN/1024)

// ---------------- scratch (device globals) ----------------
__device__ __half g_tl[(size_t)NN * DH];   // aggregation operand (fp16)
__device__ float  g_tr[(size_t)NN * DH];   // self term (fp32)
__device__ float  g_h1[(size_t)NN * DH];
__device__ float  g_h2[(size_t)NN * DH];
__device__ float  g_deginv[NN];
__device__ int    g_cnt[NN];
__device__ int    g_rowptr[NN];
__device__ int    g_cursor[NN];
__device__ int    g_col[EE];
__device__ int    g_bsum[128];

// ---------------- CSR build ----------------
__global__ void zero_cnt_kernel() {
    int i = blockIdx.x * blockDim.x + threadIdx.x;
    if (i < NN) g_cnt[i] = 0;
}

__global__ void hist_kernel(const int* __restrict__ ei) {
    int e = blockIdx.x * blockDim.x + threadIdx.x;
    if (e < EE) atomicAdd(&g_cnt[ei[EE + e]], 1);
}

__global__ void bsum_kernel() {
    __shared__ int sm[256];
    int b = blockIdx.x, t = threadIdx.x;
    int base = b * 1024 + t * 4;
    int s = 0;
#pragma unroll
    for (int i = 0; i < 4; i++) {
        int n = base + i;
        if (n < NN) s += g_cnt[n];
    }
    sm[t] = s;
    __syncthreads();
    for (int off = 128; off > 0; off >>= 1) {
        if (t < off) sm[t] += sm[t + off];
        __syncthreads();
    }
    if (t == 0) g_bsum[b] = sm[0];
}

__global__ void scan_bsum_kernel() {
    __shared__ int sm[128];
    int t = threadIdx.x;
    int v = (t < NCHUNK) ? g_bsum[t] : 0;
    sm[t] = v;
    __syncthreads();
    for (int off = 1; off < 128; off <<= 1) {
        int add = (t >= off) ? sm[t - off] : 0;
        __syncthreads();
        sm[t] += add;
        __syncthreads();
    }
    if (t < NCHUNK) g_bsum[t] = sm[t] - v;  // exclusive
}

__global__ void emit_kernel() {
    __shared__ int sm[256];
    int b = blockIdx.x, t = threadIdx.x;
    int n0 = b * 1024 + t * 4;
    int c[4];
    int tsum = 0;
#pragma unroll
    for (int i = 0; i < 4; i++) {
        c[i] = (n0 + i < NN) ? g_cnt[n0 + i] : 0;
        tsum += c[i];
    }
    sm[t] = tsum;
    __syncthreads();
    for (int off = 1; off < 256; off <<= 1) {
        int add = (t >= off) ? sm[t - off] : 0;
        __syncthreads();
        sm[t] += add;
        __syncthreads();
    }
    int base = g_bsum[b] + sm[t] - tsum;
#pragma unroll
    for (int i = 0; i < 4; i++) {
        int n = n0 + i;
        if (n < NN) {
            g_rowptr[n] = base;
            g_cursor[n] = base;
            g_deginv[n] = 1.0f / (float)max(c[i], 1);
            base += c[i];
        }
    }
}

__global__ void fill_kernel(const int* __restrict__ ei) {
    int e = blockIdx.x * blockDim.x + threadIdx.x;
    if (e < EE) {
        int d = ei[EE + e];
        int pos = atomicAdd(&g_cursor[d], 1);
        g_col[pos] = ei[e];
    }
}

// ---------------- bf16 split helpers ----------------
// pack k-pair (a = even k, b = odd k) into hi/lo bf16x2 words
__device__ __forceinline__ uint2 split_pair(float a, float b) {
    __nv_bfloat16 ha = __float2bfloat16_rn(a);
    __nv_bfloat16 hb = __float2bfloat16_rn(b);
    float ra = a - __bfloat162float(ha);
    float rb = b - __bfloat162float(hb);
    __nv_bfloat162 hi2;
    hi2.x = ha; hi2.y = hb;
    __nv_bfloat162 lo2 = __floats2bfloat162_rn(ra, rb);
    uint2 r;
    r.x = *reinterpret_cast<uint32_t*>(&hi2);
    r.y = *reinterpret_cast<uint32_t*>(&lo2);
    return r;
}

__device__ __forceinline__ void mma_bf16(float* c, uint32_t a0, uint32_t a1,
                                         uint32_t a2, uint32_t a3,
                                         uint32_t b0, uint32_t b1) {
    asm volatile(
        "mma.sync.aligned.m16n8k16.row.col.f32.bf16.bf16.f32 "
        "{%0,%1,%2,%3}, {%4,%5,%6,%7}, {%8,%9}, {%0,%1,%2,%3};\n"
        : "+f"(c[0]), "+f"(c[1]), "+f"(c[2]), "+f"(c[3])
        : "r"(a0), "r"(a1), "r"(a2), "r"(a3), "r"(b0), "r"(b1));
}

// ---------------- fused dual GEMM: Yl(fp16) = A@Wl, Yr(fp32) = A@Wr ----------------
// BM=128, BK=16 per chunk, combined N2 = 2*BNH. Warp tile 32x64.
template <int BNH>
__global__ void __launch_bounds__((BNH == 128) ? 512 : 256, 2) gemm_dual(
    const float* __restrict__ A, const float* __restrict__ Wl,
    const float* __restrict__ Wr, __half* __restrict__ Yl,
    float* __restrict__ Yr, int M) {
    constexpr int N2 = 2 * BNH;
    constexpr int THREADS = (BNH == 128) ? 512 : 256;
    constexpr int AITEMS = 512 / THREADS;       // float4 quads of A per thread
    constexpr int PERROW = N2 / 4;              // B float4 quads per k2 row
    constexpr int BITEMS = (8 * PERROW) / THREADS;  // == 1
    constexpr int AP2 = 132;                    // u2 stride (bank step 8)
    constexpr int BP2 = N2 + 4;

    __shared__ uint2 Asm[8][AP2];   // [k2][m]  .x=hi pack, .y=lo pack
    __shared__ uint2 Bsm[8][BP2];   // [k2][n]

    const int tid = threadIdx.x;
    const int lane = tid & 31, wid = tid >> 5;
    const int wm = wid & 3, wn = wid >> 2;
    const int g = lane >> 2, tig = lane & 3;
    const int m_blk = blockIdx.x * 128;

    float acc[2][8][4];
#pragma unroll
    for (int mt = 0; mt < 2; mt++)
#pragma unroll
        for (int nt = 0; nt < 8; nt++)
#pragma unroll
            for (int j = 0; j < 4; j++) acc[mt][nt][j] = 0.f;

    float4 aPre[AITEMS];
    float4 bPre0[BITEMS], bPre1[BITEMS];

    // ---- prologue: load chunk 0 ----
    {
        const int kc = 0;
#pragma unroll
        for (int i = 0; i < AITEMS; i++) {
            int idx = tid + i * THREADS;
            int m = idx >> 2, q = idx & 3;
            float4 v = make_float4(0.f, 0.f, 0.f, 0.f);
            if (m_blk + m < M) v = *(const float4*)&A[(size_t)(m_blk + m) * DH + kc + q * 4];
            aPre[i] = v;
        }
#pragma unroll
        for (int i = 0; i < BITEMS; i++) {
            int idx = tid + i * THREADS;
            int k2 = idx / PERROW, nq = idx % PERROW;
            int n0 = nq * 4;
            const float* Wp = (n0 < BNH) ? Wl : Wr;
            int col = (n0 < BNH) ? n0 : n0 - BNH;
            size_t base = (size_t)(kc + 2 * k2) * BNH + col;
            bPre0[i] = *(const float4*)&Wp[base];
            bPre1[i] = *(const float4*)&Wp[base + BNH];
        }
    }

    for (int c = 0; c < 8; c++) {
        // ---- stage regs -> smem ----
#pragma unroll
        for (int i = 0; i < AITEMS; i++) {
            int idx = tid + i * THREADS;
            int m = idx >> 2, q = idx & 3;
            Asm[2 * q][m]     = split_pair(aPre[i].x, aPre[i].y);
            Asm[2 * q + 1][m] = split_pair(aPre[i].z, aPre[i].w);
        }
#pragma unroll
        for (int i = 0; i < BITEMS; i++) {
            int idx = tid + i * THREADS;
            int k2 = idx / PERROW, nq = idx % PERROW;
            int n0 = nq * 4;
            const float* r0 = (const float*)&bPre0[i];
            const float* r1 = (const float*)&bPre1[i];
#pragma unroll
            for (int j = 0; j < 4; j++) Bsm[k2][n0 + j] = split_pair(r0[j], r1[j]);
        }
        __syncthreads();

        // ---- prefetch next chunk ----
        if (c < 7) {
            const int kc = (c + 1) * 16;
#pragma unroll
            for (int i = 0; i < AITEMS; i++) {
                int idx = tid + i * THREADS;
                int m = idx >> 2, q = idx & 3;
                float4 v = make_float4(0.f, 0.f, 0.f, 0.f);
                if (m_blk + m < M) v = *(const float4*)&A[(size_t)(m_blk + m) * DH + kc + q * 4];
                aPre[i] = v;
            }
#pragma unroll
            for (int i = 0; i < BITEMS; i++) {
                int idx = tid + i * THREADS;
                int k2 = idx / PERROW, nq = idx % PERROW;
                int n0 = nq * 4;
                const float* Wp = (n0 < BNH) ? Wl : Wr;
                int col = (n0 < BNH) ? n0 : n0 - BNH;
                size_t base = (size_t)(kc + 2 * k2) * BNH + col;
                bPre0[i] = *(const float4*)&Wp[base];
                bPre1[i] = *(const float4*)&Wp[base + BNH];
            }
        }

        // ---- mma sweep (one k16 step) ----
        uint2 af[2][4];
#pragma unroll
        for (int mt = 0; mt < 2; mt++) {
            int r0 = wm * 32 + mt * 16 + g;
            af[mt][0] = Asm[tig][r0];
            af[mt][1] = Asm[tig][r0 + 8];
            af[mt][2] = Asm[tig + 4][r0];
            af[mt][3] = Asm[tig + 4][r0 + 8];
        }
#pragma unroll
        for (int nt = 0; nt < 8; nt++) {
            int n = wn * 64 + nt * 8 + g;
            uint2 b0 = Bsm[tig][n];
            uint2 b1 = Bsm[tig + 4][n];
#pragma unroll
            for (int mt = 0; mt < 2; mt++) {
                mma_bf16(acc[mt][nt], af[mt][0].x, af[mt][1].x, af[mt][2].x, af[mt][3].x, b0.x, b1.x);  // hi*hi
                mma_bf16(acc[mt][nt], af[mt][0].x, af[mt][1].x, af[mt][2].x, af[mt][3].x, b0.y, b1.y);  // hi*lo
                mma_bf16(acc[mt][nt], af[mt][0].y, af[mt][1].y, af[mt][2].y, af[mt][3].y, b0.x, b1.x);  // lo*hi
            }
        }
        __syncthreads();
    }

    // ---- epilogue: Yl as fp16, Yr as fp32 ----
#pragma unroll
    for (int mt = 0; mt < 2; mt++) {
        int r0 = m_blk + wm * 32 + mt * 16 + g;
#pragma unroll
        for (int nt = 0; nt < 8; nt++) {
            int n2 = wn * 64 + nt * 8 + 2 * tig;
            if (n2 < BNH) {
                if (r0 < M)
                    *(__half2*)&Yl[(size_t)r0 * BNH + n2] =
                        __floats2half2_rn(acc[mt][nt][0], acc[mt][nt][1]);
                if (r0 + 8 < M)
                    *(__half2*)&Yl[(size_t)(r0 + 8) * BNH + n2] =
                        __floats2half2_rn(acc[mt][nt][2], acc[mt][nt][3]);
            } else {
                int colb = n2 - BNH;
                if (r0 < M)
                    *(float2*)&Yr[(size_t)r0 * BNH + colb] = make_float2(acc[mt][nt][0], acc[mt][nt][1]);
                if (r0 + 8 < M)
                    *(float2*)&Yr[(size_t)(r0 + 8) * BNH + colb] = make_float2(acc[mt][nt][2], acc[mt][nt][3]);
            }
        }
    }
}

// ---------------- aggregate(fp16 gather) + bias + self + ReLU (width 128) ----------------
__device__ __forceinline__ void acc_row128(const __half* tl, int row, int lane,
                                           float& ax, float& ay, float& az, float& aw) {
    uint2 u = *(const uint2*)&tl[(size_t)row * DH + lane * 4];
    float2 f0 = __half22float2(*(__half2*)&u.x);
    float2 f1 = __half22float2(*(__half2*)&u.y);
    ax += f0.x; ay += f0.y; az += f1.x; aw += f1.y;
}

__global__ void agg_combine128(const __half* __restrict__ tl, const float* __restrict__ tr,
                               const float* __restrict__ bias, float* __restrict__ out) {
    int node = (blockIdx.x * blockDim.x + threadIdx.x) >> 5;
    int lane = threadIdx.x & 31;
    if (node >= NN) return;
    int start = g_rowptr[node];
    int cnt = g_cnt[node];
    float ax = 0.f, ay = 0.f, az = 0.f, aw = 0.f;
    int j = 0;
    while (j < cnt) {
        int batch = min(cnt - j, 32);
        int s = (lane < batch) ? g_col[start + j + lane] : 0;
        int t = 0;
        for (; t + 4 <= batch; t += 4) {
            int s0 = __shfl_sync(0xffffffffu, s, t);
            int s1 = __shfl_sync(0xffffffffu, s, t + 1);
            int s2 = __shfl_sync(0xffffffffu, s, t + 2);
            int s3 = __shfl_sync(0xffffffffu, s, t + 3);
            acc_row128(tl, s0, lane, ax, ay, az, aw);
            acc_row128(tl, s1, lane, ax, ay, az, aw);
            acc_row128(tl, s2, lane, ax, ay, az, aw);
            acc_row128(tl, s3, lane, ax, ay, az, aw);
        }
        for (; t < batch; t++) {
            int sv = __shfl_sync(0xffffffffu, s, t);
            acc_row128(tl, sv, lane, ax, ay, az, aw);
        }
        j += batch;
    }
    float sc = g_deginv[node];
    float4 b = *(const float4*)&bias[lane * 4];
    float4 r = *(const float4*)&tr[(size_t)node * DH + lane * 4];
    float4 o = make_float4(fmaxf(ax * sc + b.x + r.x, 0.f),
                           fmaxf(ay * sc + b.y + r.y, 0.f),
                           fmaxf(az * sc + b.z + r.z, 0.f),
                           fmaxf(aw * sc + b.w + r.w, 0.f));
    *(float4*)&out[(size_t)node * DH + lane * 4] = o;
}

// ---------------- layer-3: aggregate (width 64, fp16) + bias + self + L2 normalize ----------------
__global__ void agg_norm64(const __half* __restrict__ tl, const float* __restrict__ tr,
                           const float* __restrict__ bias, float* __restrict__ out) {
    int node = (blockIdx.x * blockDim.x + threadIdx.x) >> 5;
    int lane = threadIdx.x & 31;
    if (node >= NN) return;
    int start = g_rowptr[node];
    int cnt = g_cnt[node];
    float ax = 0.f, ay = 0.f;
    int j = 0;
    while (j < cnt) {
        int batch = min(cnt - j, 32);
        int s = (lane < batch) ? g_col[start + j + lane] : 0;
        int t = 0;
        for (; t + 4 <= batch; t += 4) {
            int s0 = __shfl_sync(0xffffffffu, s, t);
            int s1 = __shfl_sync(0xffffffffu, s, t + 1);
            int s2 = __shfl_sync(0xffffffffu, s, t + 2);
            int s3 = __shfl_sync(0xffffffffu, s, t + 3);
            float2 v0 = __half22float2(*(const __half2*)&tl[(size_t)s0 * DOUT + lane * 2]);
            float2 v1 = __half22float2(*(const __half2*)&tl[(size_t)s1 * DOUT + lane * 2]);
            float2 v2 = __half22float2(*(const __half2*)&tl[(size_t)s2 * DOUT + lane * 2]);
            float2 v3 = __half22float2(*(const __half2*)&tl[(size_t)s3 * DOUT + lane * 2]);
            ax += v0.x + v1.x + v2.x + v3.x;
            ay += v0.y + v1.y + v2.y + v3.y;
        }
        for (; t < batch; t++) {
            int sv = __shfl_sync(0xffffffffu, s, t);
            float2 v = __half22float2(*(const __half2*)&tl[(size_t)sv * DOUT + lane * 2]);
            ax += v.x; ay += v.y;
        }
        j += batch;
    }
    float sc = g_deginv[node];
    float2 b = *(const float2*)&bias[lane * 2];
    float2 r = *(const float2*)&tr[(size_t)node * DOUT + lane * 2];
    float yx = ax * sc + b.x + r.x;
    float yy = ay * sc + b.y + r.y;
    float ss = yx * yx + yy * yy;
#pragma unroll
    for (int off = 16; off > 0; off >>= 1) ss += __shfl_xor_sync(0xffffffffu, ss, off);
    float inv = 1.0f / fmaxf(sqrtf(ss), 1e-12f);
    *(float2*)&out[(size_t)node * DOUT + lane * 2] = make_float2(yx * inv, yy * inv);
}

// ---------------- launch ----------------
extern "C" void kernel_launch(void* const* d_in, const int* in_sizes, int n_in,
                              void* d_out, int out_size) {
    const float* x   = (const float*)d_in[0];
    const int*   ei  = (const int*)d_in[1];
    const float* Wl1 = (const float*)d_in[2];
    const float* bl1 = (const float*)d_in[3];
    const float* Wr1 = (const float*)d_in[4];
    const float* Wl2 = (const float*)d_in[5];
    const float* bl2 = (const float*)d_in[6];
    const float* Wr2 = (const float*)d_in[7];
    const float* Wl3 = (const float*)d_in[8];
    const float* bl3 = (const float*)d_in[9];
    const float* Wr3 = (const float*)d_in[10];
    float* out = (float*)d_out;

    void *ptl, *ptr, *p1, *p2;
    cudaGetSymbolAddress(&ptl, g_tl);
    cudaGetSymbolAddress(&ptr, g_tr);
    cudaGetSymbolAddress(&p1, g_h1);
    cudaGetSymbolAddress(&p2, g_h2);
    __half* tl = (__half*)ptl;
    float* tr = (float*)ptr;
    float* h1 = (float*)p1;
    float* h2 = (float*)p2;

    const int GB = (NN + 127) / 128;
    const int AB = (NN + 7) / 8;

    // CSR build front (5 launches) so ncu skip-5 lands on the first gemm
    zero_cnt_kernel<<<(NN + 255) / 256, 256>>>();
    hist_kernel<<<(EE + 255) / 256, 256>>>(ei);
    bsum_kernel<<<NCHUNK, 256>>>();
    scan_bsum_kernel<<<1, 128>>>();
    emit_kernel<<<NCHUNK, 256>>>();

    // layer 1
    gemm_dual<128><<<GB, 512>>>(x, Wl1, Wr1, tl, tr, NN);
    fill_kernel<<<(EE + 255) / 256, 256>>>(ei);
    agg_combine128<<<AB, 256>>>(tl, tr, bl1, h1);
    // layer 2
    gemm_dual<128><<<GB, 512>>>(h1, Wl2, Wr2, tl, tr, NN);
    agg_combine128<<<AB, 256>>>(tl, tr, bl2, h2);
    // layer 3 (width 64) + fused L2 normalize
    gemm_dual<64><<<GB, 256>>>(h2, Wl3, Wr3, tl, tr, NN);
    agg_norm64<<<AB, 256>>>(tl, tr, bl3, out);
}

// round 6
// speedup vs baseline: 1.2626x; 1.2626x over previous
#include <cuda_runtime.h>
#include <cuda_bf16.h>
#include <cuda_fp16.h>
#include <math.h>
#include <stdint.h>

#define NN 100000
#define EE 1600000
#define DH 128
#define DOUT 64
#define NCHUNK 98   // ceil(NN/1024)

// ---------------- scratch (device globals) ----------------
__device__ __half g_tl[(size_t)NN * DH];   // aggregation operand (fp16)
__device__ float  g_tr[(size_t)NN * DH];   // self term (fp32)
__device__ float  g_h1[(size_t)NN * DH];
__device__ float  g_h2[(size_t)NN * DH];
__device__ float  g_deginv[NN];
__device__ int    g_cnt[NN];
__device__ int    g_rowptr[NN];
__device__ int    g_cursor[NN];
__device__ int    g_col[EE];
__device__ int    g_bsum[128];

// ---------------- CSR build ----------------
__global__ void zero_cnt_kernel() {
    int i = blockIdx.x * blockDim.x + threadIdx.x;
    if (i < NN) g_cnt[i] = 0;
}

__global__ void hist_kernel(const int* __restrict__ ei) {
    int e = blockIdx.x * blockDim.x + threadIdx.x;
    if (e < EE) atomicAdd(&g_cnt[ei[EE + e]], 1);
}

__global__ void bsum_kernel() {
    __shared__ int sm[256];
    int b = blockIdx.x, t = threadIdx.x;
    int base = b * 1024 + t * 4;
    int s = 0;
#pragma unroll
    for (int i = 0; i < 4; i++) {
        int n = base + i;
        if (n < NN) s += g_cnt[n];
    }
    sm[t] = s;
    __syncthreads();
    for (int off = 128; off > 0; off >>= 1) {
        if (t < off) sm[t] += sm[t + off];
        __syncthreads();
    }
    if (t == 0) g_bsum[b] = sm[0];
}

__global__ void scan_bsum_kernel() {
    __shared__ int sm[128];
    int t = threadIdx.x;
    int v = (t < NCHUNK) ? g_bsum[t] : 0;
    sm[t] = v;
    __syncthreads();
    for (int off = 1; off < 128; off <<= 1) {
        int add = (t >= off) ? sm[t - off] : 0;
        __syncthreads();
        sm[t] += add;
        __syncthreads();
    }
    if (t < NCHUNK) g_bsum[t] = sm[t] - v;  // exclusive
}

__global__ void emit_kernel() {
    __shared__ int sm[256];
    int b = blockIdx.x, t = threadIdx.x;
    int n0 = b * 1024 + t * 4;
    int c[4];
    int tsum = 0;
#pragma unroll
    for (int i = 0; i < 4; i++) {
        c[i] = (n0 + i < NN) ? g_cnt[n0 + i] : 0;
        tsum += c[i];
    }
    sm[t] = tsum;
    __syncthreads();
    for (int off = 1; off < 256; off <<= 1) {
        int add = (t >= off) ? sm[t - off] : 0;
        __syncthreads();
        sm[t] += add;
        __syncthreads();
    }
    int base = g_bsum[b] + sm[t] - tsum;
#pragma unroll
    for (int i = 0; i < 4; i++) {
        int n = n0 + i;
        if (n < NN) {
            g_rowptr[n] = base;
            g_cursor[n] = base;
            g_deginv[n] = 1.0f / (float)max(c[i], 1);
            base += c[i];
        }
    }
}

__global__ void fill_kernel(const int* __restrict__ ei) {
    int e = blockIdx.x * blockDim.x + threadIdx.x;
    if (e < EE) {
        int d = ei[EE + e];
        int pos = atomicAdd(&g_cursor[d], 1);
        g_col[pos] = ei[e];
    }
}

// ---------------- bf16 split helpers ----------------
// pack k-pair (a = even k, b = odd k) into hi/lo bf16x2 words
__device__ __forceinline__ uint2 split_pair(float a, float b) {
    __nv_bfloat16 ha = __float2bfloat16_rn(a);
    __nv_bfloat16 hb = __float2bfloat16_rn(b);
    float ra = a - __bfloat162float(ha);
    float rb = b - __bfloat162float(hb);
    __nv_bfloat162 hi2;
    hi2.x = ha; hi2.y = hb;
    __nv_bfloat162 lo2 = __floats2bfloat162_rn(ra, rb);
    uint2 r;
    r.x = *reinterpret_cast<uint32_t*>(&hi2);
    r.y = *reinterpret_cast<uint32_t*>(&lo2);
    return r;
}

__device__ __forceinline__ void mma_bf16(float* c, uint32_t a0, uint32_t a1,
                                         uint32_t a2, uint32_t a3,
                                         uint32_t b0, uint32_t b1) {
    asm volatile(
        "mma.sync.aligned.m16n8k16.row.col.f32.bf16.bf16.f32 "
        "{%0,%1,%2,%3}, {%4,%5,%6,%7}, {%8,%9}, {%0,%1,%2,%3};\n"
        : "+f"(c[0]), "+f"(c[1]), "+f"(c[2]), "+f"(c[3])
        : "r"(a0), "r"(a1), "r"(a2), "r"(a3), "r"(b0), "r"(b1));
}

// ---------------- fused dual GEMM: Yl(fp16) = A@Wl, Yr(fp32) = A@Wr ----------------
// BM=128, BK=16 per chunk, combined N2 = 2*BNH. Warp tile 32x64.
template <int BNH>
__global__ void __launch_bounds__((BNH == 128) ? 512 : 256, 1) gemm_dual(
    const float* __restrict__ A, const float* __restrict__ Wl,
    const float* __restrict__ Wr, __half* __restrict__ Yl,
    float* __restrict__ Yr, int M) {
    constexpr int N2 = 2 * BNH;
    constexpr int THREADS = (BNH == 128) ? 512 : 256;
    constexpr int AITEMS = 512 / THREADS;       // float4 quads of A per thread
    constexpr int PERROW = N2 / 4;              // B float4 quads per k2 row
    constexpr int BITEMS = (8 * PERROW) / THREADS;  // == 1
    constexpr int AP2 = 132;                    // u2 stride (bank step 8)
    constexpr int BP2 = N2 + 4;

    __shared__ uint2 Asm[8][AP2];   // [k2][m]  .x=hi pack, .y=lo pack
    __shared__ uint2 Bsm[8][BP2];   // [k2][n]

    const int tid = threadIdx.x;
    const int lane = tid & 31, wid = tid >> 5;
    const int wm = wid & 3, wn = wid >> 2;
    const int g = lane >> 2, tig = lane & 3;
    const int m_blk = blockIdx.x * 128;

    float acc[2][8][4];
#pragma unroll
    for (int mt = 0; mt < 2; mt++)
#pragma unroll
        for (int nt = 0; nt < 8; nt++)
#pragma unroll
            for (int j = 0; j < 4; j++) acc[mt][nt][j] = 0.f;

    float4 aPre[AITEMS];
    float4 bPre0[BITEMS], bPre1[BITEMS];

    // ---- prologue: load chunk 0 ----
    {
        const int kc = 0;
#pragma unroll
        for (int i = 0; i < AITEMS; i++) {
            int idx = tid + i * THREADS;
            int m = idx >> 2, q = idx & 3;
            float4 v = make_float4(0.f, 0.f, 0.f, 0.f);
            if (m_blk + m < M) v = *(const float4*)&A[(size_t)(m_blk + m) * DH + kc + q * 4];
            aPre[i] = v;
        }
#pragma unroll
        for (int i = 0; i < BITEMS; i++) {
            int idx = tid + i * THREADS;
            int k2 = idx / PERROW, nq = idx % PERROW;
            int n0 = nq * 4;
            const float* Wp = (n0 < BNH) ? Wl : Wr;
            int col = (n0 < BNH) ? n0 : n0 - BNH;
            size_t base = (size_t)(kc + 2 * k2) * BNH + col;
            bPre0[i] = *(const float4*)&Wp[base];
            bPre1[i] = *(const float4*)&Wp[base + BNH];
        }
    }

    for (int c = 0; c < 8; c++) {
        // ---- stage regs -> smem ----
#pragma unroll
        for (int i = 0; i < AITEMS; i++) {
            int idx = tid + i * THREADS;
            int m = idx >> 2, q = idx & 3;
            Asm[2 * q][m]     = split_pair(aPre[i].x, aPre[i].y);
            Asm[2 * q + 1][m] = split_pair(aPre[i].z, aPre[i].w);
        }
#pragma unroll
        for (int i = 0; i < BITEMS; i++) {
            int idx = tid + i * THREADS;
            int k2 = idx / PERROW, nq = idx % PERROW;
            int n0 = nq * 4;
            const float* r0 = (const float*)&bPre0[i];
            const float* r1 = (const float*)&bPre1[i];
#pragma unroll
            for (int j = 0; j < 4; j++) Bsm[k2][n0 + j] = split_pair(r0[j], r1[j]);
        }
        __syncthreads();

        // ---- prefetch next chunk ----
        if (c < 7) {
            const int kc = (c + 1) * 16;
#pragma unroll
            for (int i = 0; i < AITEMS; i++) {
                int idx = tid + i * THREADS;
                int m = idx >> 2, q = idx & 3;
                float4 v = make_float4(0.f, 0.f, 0.f, 0.f);
                if (m_blk + m < M) v = *(const float4*)&A[(size_t)(m_blk + m) * DH + kc + q * 4];
                aPre[i] = v;
            }
#pragma unroll
            for (int i = 0; i < BITEMS; i++) {
                int idx = tid + i * THREADS;
                int k2 = idx / PERROW, nq = idx % PERROW;
                int n0 = nq * 4;
                const float* Wp = (n0 < BNH) ? Wl : Wr;
                int col = (n0 < BNH) ? n0 : n0 - BNH;
                size_t base = (size_t)(kc + 2 * k2) * BNH + col;
                bPre0[i] = *(const float4*)&Wp[base];
                bPre1[i] = *(const float4*)&Wp[base + BNH];
            }
        }

        // ---- mma sweep (one k16 step) ----
        uint2 af[2][4];
#pragma unroll
        for (int mt = 0; mt < 2; mt++) {
            int r0 = wm * 32 + mt * 16 + g;
            af[mt][0] = Asm[tig][r0];
            af[mt][1] = Asm[tig][r0 + 8];
            af[mt][2] = Asm[tig + 4][r0];
            af[mt][3] = Asm[tig + 4][r0 + 8];
        }
#pragma unroll
        for (int nt = 0; nt < 8; nt++) {
            int n = wn * 64 + nt * 8 + g;
            uint2 b0 = Bsm[tig][n];
            uint2 b1 = Bsm[tig + 4][n];
#pragma unroll
            for (int mt = 0; mt < 2; mt++) {
                mma_bf16(acc[mt][nt], af[mt][0].x, af[mt][1].x, af[mt][2].x, af[mt][3].x, b0.x, b1.x);  // hi*hi
                mma_bf16(acc[mt][nt], af[mt][0].x, af[mt][1].x, af[mt][2].x, af[mt][3].x, b0.y, b1.y);  // hi*lo
                mma_bf16(acc[mt][nt], af[mt][0].y, af[mt][1].y, af[mt][2].y, af[mt][3].y, b0.x, b1.x);  // lo*hi
            }
        }
        __syncthreads();
    }

    // ---- epilogue: Yl as fp16, Yr as fp32 ----
#pragma unroll
    for (int mt = 0; mt < 2; mt++) {
        int r0 = m_blk + wm * 32 + mt * 16 + g;
#pragma unroll
        for (int nt = 0; nt < 8; nt++) {
            int n2 = wn * 64 + nt * 8 + 2 * tig;
            if (n2 < BNH) {
                if (r0 < M)
                    *(__half2*)&Yl[(size_t)r0 * BNH + n2] =
                        __floats2half2_rn(acc[mt][nt][0], acc[mt][nt][1]);
                if (r0 + 8 < M)
                    *(__half2*)&Yl[(size_t)(r0 + 8) * BNH + n2] =
                        __floats2half2_rn(acc[mt][nt][2], acc[mt][nt][3]);
            } else {
                int colb = n2 - BNH;
                if (r0 < M)
                    *(float2*)&Yr[(size_t)r0 * BNH + colb] = make_float2(acc[mt][nt][0], acc[mt][nt][1]);
                if (r0 + 8 < M)
                    *(float2*)&Yr[(size_t)(r0 + 8) * BNH + colb] = make_float2(acc[mt][nt][2], acc[mt][nt][3]);
            }
        }
    }
}

// ---------------- aggregate(fp16 gather) + bias + self + ReLU (width 128) ----------------
__device__ __forceinline__ void acc_row128(const __half* tl, int row, int lane,
                                           float& ax, float& ay, float& az, float& aw) {
    uint2 u = *(const uint2*)&tl[(size_t)row * DH + lane * 4];
    float2 f0 = __half22float2(*(__half2*)&u.x);
    float2 f1 = __half22float2(*(__half2*)&u.y);
    ax += f0.x; ay += f0.y; az += f1.x; aw += f1.y;
}

__global__ void agg_combine128(const __half* __restrict__ tl, const float* __restrict__ tr,
                               const float* __restrict__ bias, float* __restrict__ out) {
    int node = (blockIdx.x * blockDim.x + threadIdx.x) >> 5;
    int lane = threadIdx.x & 31;
    if (node >= NN) return;
    int start = g_rowptr[node];
    int cnt = g_cnt[node];
    float ax = 0.f, ay = 0.f, az = 0.f, aw = 0.f;
    int j = 0;
    while (j < cnt) {
        int batch = min(cnt - j, 32);
        int s = (lane < batch) ? g_col[start + j + lane] : 0;
        int t = 0;
        for (; t + 4 <= batch; t += 4) {
            int s0 = __shfl_sync(0xffffffffu, s, t);
            int s1 = __shfl_sync(0xffffffffu, s, t + 1);
            int s2 = __shfl_sync(0xffffffffu, s, t + 2);
            int s3 = __shfl_sync(0xffffffffu, s, t + 3);
            acc_row128(tl, s0, lane, ax, ay, az, aw);
            acc_row128(tl, s1, lane, ax, ay, az, aw);
            acc_row128(tl, s2, lane, ax, ay, az, aw);
            acc_row128(tl, s3, lane, ax, ay, az, aw);
        }
        for (; t < batch; t++) {
            int sv = __shfl_sync(0xffffffffu, s, t);
            acc_row128(tl, sv, lane, ax, ay, az, aw);
        }
        j += batch;
    }
    float sc = g_deginv[node];
    float4 b = *(const float4*)&bias[lane * 4];
    float4 r = *(const float4*)&tr[(size_t)node * DH + lane * 4];
    float4 o = make_float4(fmaxf(ax * sc + b.x + r.x, 0.f),
                           fmaxf(ay * sc + b.y + r.y, 0.f),
                           fmaxf(az * sc + b.z + r.z, 0.f),
                           fmaxf(aw * sc + b.w + r.w, 0.f));
    *(float4*)&out[(size_t)node * DH + lane * 4] = o;
}

// ---------------- layer-3: aggregate (width 64, fp16) + bias + self + L2 normalize ----------------
__global__ void agg_norm64(const __half* __restrict__ tl, const float* __restrict__ tr,
                           const float* __restrict__ bias, float* __restrict__ out) {
    int node = (blockIdx.x * blockDim.x + threadIdx.x) >> 5;
    int lane = threadIdx.x & 31;
    if (node >= NN) return;
    int start = g_rowptr[node];
    int cnt = g_cnt[node];
    float ax = 0.f, ay = 0.f;
    int j = 0;
    while (j < cnt) {
        int batch = min(cnt - j, 32);
        int s = (lane < batch) ? g_col[start + j + lane] : 0;
        int t = 0;
        for (; t + 4 <= batch; t += 4) {
            int s0 = __shfl_sync(0xffffffffu, s, t);
            int s1 = __shfl_sync(0xffffffffu, s, t + 1);
            int s2 = __shfl_sync(0xffffffffu, s, t + 2);
            int s3 = __shfl_sync(0xffffffffu, s, t + 3);
            float2 v0 = __half22float2(*(const __half2*)&tl[(size_t)s0 * DOUT + lane * 2]);
            float2 v1 = __half22float2(*(const __half2*)&tl[(size_t)s1 * DOUT + lane * 2]);
            float2 v2 = __half22float2(*(const __half2*)&tl[(size_t)s2 * DOUT + lane * 2]);
            float2 v3 = __half22float2(*(const __half2*)&tl[(size_t)s3 * DOUT + lane * 2]);
            ax += v0.x + v1.x + v2.x + v3.x;
            ay += v0.y + v1.y + v2.y + v3.y;
        }
        for (; t < batch; t++) {
            int sv = __shfl_sync(0xffffffffu, s, t);
            float2 v = __half22float2(*(const __half2*)&tl[(size_t)sv * DOUT + lane * 2]);
            ax += v.x; ay += v.y;
        }
        j += batch;
    }
    float sc = g_deginv[node];
    float2 b = *(const float2*)&bias[lane * 2];
    float2 r = *(const float2*)&tr[(size_t)node * DOUT + lane * 2];
    float yx = ax * sc + b.x + r.x;
    float yy = ay * sc + b.y + r.y;
    float ss = yx * yx + yy * yy;
#pragma unroll
    for (int off = 16; off > 0; off >>= 1) ss += __shfl_xor_sync(0xffffffffu, ss, off);
    float inv = 1.0f / fmaxf(sqrtf(ss), 1e-12f);
    *(float2*)&out[(size_t)node * DOUT + lane * 2] = make_float2(yx * inv, yy * inv);
}

// ---------------- launch ----------------
extern "C" void kernel_launch(void* const* d_in, const int* in_sizes, int n_in,
                              void* d_out, int out_size) {
    const float* x   = (const float*)d_in[0];
    const int*   ei  = (const int*)d_in[1];
    const float* Wl1 = (const float*)d_in[2];
    const float* bl1 = (const float*)d_in[3];
    const float* Wr1 = (const float*)d_in[4];
    const float* Wl2 = (const float*)d_in[5];
    const float* bl2 = (const float*)d_in[6];
    const float* Wr2 = (const float*)d_in[7];
    const float* Wl3 = (const float*)d_in[8];
    const float* bl3 = (const float*)d_in[9];
    const float* Wr3 = (const float*)d_in[10];
    float* out = (float*)d_out;

    void *ptl, *ptr, *p1, *p2;
    cudaGetSymbolAddress(&ptl, g_tl);
    cudaGetSymbolAddress(&ptr, g_tr);
    cudaGetSymbolAddress(&p1, g_h1);
    cudaGetSymbolAddress(&p2, g_h2);
    __half* tl = (__half*)ptl;
    float* tr = (float*)ptr;
    float* h1 = (float*)p1;
    float* h2 = (float*)p2;

    const int GB = (NN + 127) / 128;
    const int AB = (NN + 7) / 8;

    // CSR build front (5 launches) so ncu skip-5 lands on the first gemm
    zero_cnt_kernel<<<(NN + 255) / 256, 256>>>();
    hist_kernel<<<(EE + 255) / 256, 256>>>(ei);
    bsum_kernel<<<NCHUNK, 256>>>();
    scan_bsum_kernel<<<1, 128>>>();
    emit_kernel<<<NCHUNK, 256>>>();

    // layer 1
    gemm_dual<128><<<GB, 512>>>(x, Wl1, Wr1, tl, tr, NN);
    fill_kernel<<<(EE + 255) / 256, 256>>>(ei);
    agg_combine128<<<AB, 256>>>(tl, tr, bl1, h1);
    // layer 2
    gemm_dual<128><<<GB, 512>>>(h1, Wl2, Wr2, tl, tr, NN);
    agg_combine128<<<AB, 256>>>(tl, tr, bl2, h2);
    // layer 3 (width 64) + fused L2 normalize
    gemm_dual<64><<<GB, 256>>>(h2, Wl3, Wr3, tl, tr, NN);
    agg_norm64<<<AB, 256>>>(tl, tr, bl3, out);
}